// round 1
// baseline (speedup 1.0000x reference)
#include <cuda_runtime.h>

#define T_DIM 256
#define D_DIM 44
#define H_DIM 8
#define NPATHS 8192
#define NGROUPS 1024
#define WARPS_PER_BLK 8

// scratch: h at last valid timestep, [NPATHS, H]
__device__ float g_hlast[NPATHS * H_DIM];

__device__ __forceinline__ float fast_ex2(float x) {
    float r; asm("ex2.approx.f32 %0, %1;" : "=f"(r) : "f"(x)); return r;
}
__device__ __forceinline__ float fast_rcp(float x) {
    float r; asm("rcp.approx.f32 %0, %1;" : "=f"(r) : "f"(x)); return r;
}
// tanh(x) = 1 - 2/(1 + exp(2x));  exp(2x) = ex2(x * 2*log2(e))
__device__ __forceinline__ float tanh_f(float x) {
    float e = fast_ex2(2.8853900817779268f * x);
    return 1.0f - 2.0f * fast_rcp(e + 1.0f);
}

__global__ void __launch_bounds__(32 * WARPS_PER_BLK)
lstm_kernel(const float* __restrict__ x,
            const float* __restrict__ W_ih,
            const float* __restrict__ W_hh,
            const float* __restrict__ b_ih,
            const float* __restrict__ b_hh,
            const int* __restrict__ last_idx)
{
    __shared__ float4 sx[WARPS_PER_BLK][2][12];  // double-buffered x_t per warp

    const int w    = threadIdx.x >> 5;
    const int lane = threadIdx.x & 31;
    const int path = blockIdx.x * WARPS_PER_BLK + w;

    // lane g owns gate row g of W_ih / W_hh (rows: 0-7 i, 8-15 f, 16-23 g, 24-31 o)
    float wih[44];
    {
        const float4* wr = (const float4*)(W_ih + lane * 44);  // 176B rows -> 16B aligned
        #pragma unroll
        for (int k = 0; k < 11; k++) {
            float4 v = wr[k];
            wih[4*k+0] = v.x; wih[4*k+1] = v.y; wih[4*k+2] = v.z; wih[4*k+3] = v.w;
        }
    }
    float whh[8];
    {
        const float4* wr = (const float4*)(W_hh + lane * 8);
        float4 v0 = wr[0], v1 = wr[1];
        whh[0]=v0.x; whh[1]=v0.y; whh[2]=v0.z; whh[3]=v0.w;
        whh[4]=v1.x; whh[5]=v1.y; whh[6]=v1.z; whh[7]=v1.w;
    }
    const float bias = b_ih[lane] + b_hh[lane];

    // branchless activation params:  act(x) = al + be * rcp(1 + ex2(m*x))
    //   sigmoid: m = -log2(e),   al = 0, be = 1
    //   tanh   : m = 2*log2(e),  al = 1, be = -2
    const bool isg = (lane >= 16) && (lane < 24);
    const float m_act  = isg ?  2.8853900817779268f : -1.4426950408889634f;
    const float al_act = isg ?  1.0f : 0.0f;
    const float be_act = isg ? -2.0f : 1.0f;

    const int   last = last_idx[path];
    const float* xr  = x + (size_t)path * T_DIM * D_DIM;
    const int   jl   = lane & 7;

    float hvec[8];
    #pragma unroll
    for (int j = 0; j < 8; j++) hvec[j] = 0.0f;
    float c = 0.0f;

    // prologue: stage x_0
    if (lane < 11) sx[w][0][lane] = ((const float4*)xr)[lane];
    __syncwarp();

    for (int t = 0; t <= last; t++) {
        const int cur = t & 1;

        // prefetch x_{t+1} while computing step t
        float4 vn;
        const bool pf = (lane < 11) && (t < last);
        if (pf) vn = ((const float4*)(xr + (size_t)(t + 1) * D_DIM))[lane];

        float acc = bias;
        #pragma unroll
        for (int k = 0; k < 11; k++) {
            float4 xv = sx[w][cur][k];     // warp-uniform broadcast LDS.128
            acc = fmaf(wih[4*k+0], xv.x, acc);
            acc = fmaf(wih[4*k+1], xv.y, acc);
            acc = fmaf(wih[4*k+2], xv.z, acc);
            acc = fmaf(wih[4*k+3], xv.w, acc);
        }
        #pragma unroll
        for (int j = 0; j < 8; j++) acc = fmaf(whh[j], hvec[j], acc);

        // branchless per-lane activation
        float u = fast_rcp(1.0f + fast_ex2(m_act * acc));
        float a = fmaf(be_act, u, al_act);

        // gather i/f/g/o for hidden index jl
        float iv = __shfl_sync(0xffffffffu, a, jl);
        float fv = __shfl_sync(0xffffffffu, a, jl + 8);
        float gv = __shfl_sync(0xffffffffu, a, jl + 16);
        float ov = __shfl_sync(0xffffffffu, a, jl + 24);

        c = fmaf(fv, c, iv * gv);
        float hl = ov * tanh_f(c);

        #pragma unroll
        for (int j = 0; j < 8; j++) hvec[j] = __shfl_sync(0xffffffffu, hl, j);

        if (pf) sx[w][cur ^ 1][lane] = vn;
        __syncwarp();
    }

    if (lane < 8) g_hlast[path * H_DIM + lane] = hvec[lane];
}

// segment-sum (sorted group_ids, binary search -> deterministic) + fc + softmax
__global__ void __launch_bounds__(NGROUPS)
finalize_kernel(const int* __restrict__ group_ids,
                const float* __restrict__ fc_W,
                const float* __restrict__ fc_b,
                float* __restrict__ out)
{
    __shared__ float red[NGROUPS];
    const int g = threadIdx.x;

    float w[8];
    #pragma unroll
    for (int j = 0; j < 8; j++) w[j] = fc_W[j];

    // lower_bound(g) and upper_bound(g) over sorted group_ids[0..NPATHS)
    int lo = 0, hi = NPATHS;
    while (lo < hi) { int mid = (lo + hi) >> 1; if (group_ids[mid] <  g) lo = mid + 1; else hi = mid; }
    const int start = lo;
    hi = NPATHS;
    while (lo < hi) { int mid = (lo + hi) >> 1; if (group_ids[mid] <= g) lo = mid + 1; else hi = mid; }
    const int end = lo;

    float logit = fc_b[0];
    for (int n = start; n < end; n++) {
        const float4* hp = (const float4*)(g_hlast + n * H_DIM);
        float4 h0 = hp[0], h1 = hp[1];
        float s = h0.x * w[0];
        s = fmaf(h0.y, w[1], s);
        s = fmaf(h0.z, w[2], s);
        s = fmaf(h0.w, w[3], s);
        s = fmaf(h1.x, w[4], s);
        s = fmaf(h1.y, w[5], s);
        s = fmaf(h1.z, w[6], s);
        s = fmaf(h1.w, w[7], s);
        logit += s;
    }

    // softmax over the 1024 groups
    red[g] = logit;
    __syncthreads();
    #pragma unroll
    for (int off = NGROUPS / 2; off > 0; off >>= 1) {
        if (g < off) red[g] = fmaxf(red[g], red[g + off]);
        __syncthreads();
    }
    const float mx = red[0];
    __syncthreads();
    const float e = __expf(logit - mx);
    red[g] = e;
    __syncthreads();
    #pragma unroll
    for (int off = NGROUPS / 2; off > 0; off >>= 1) {
        if (g < off) red[g] += red[g + off];
        __syncthreads();
    }
    out[g] = e * fast_rcp(red[0]);
}

extern "C" void kernel_launch(void* const* d_in, const int* in_sizes, int n_in,
                              void* d_out, int out_size)
{
    const float* x      = (const float*)d_in[0];
    const float* W_ih   = (const float*)d_in[1];
    const float* W_hh   = (const float*)d_in[2];
    const float* b_ih   = (const float*)d_in[3];
    const float* b_hh   = (const float*)d_in[4];
    const float* fc_W   = (const float*)d_in[5];
    const float* fc_b   = (const float*)d_in[6];
    const int*   last_i = (const int*)d_in[7];
    const int*   gids   = (const int*)d_in[8];
    float*       out    = (float*)d_out;

    lstm_kernel<<<NPATHS / WARPS_PER_BLK, 32 * WARPS_PER_BLK>>>(
        x, W_ih, W_hh, b_ih, b_hh, last_i);
    finalize_kernel<<<1, NGROUPS>>>(gids, fc_W, fc_b, out);
}

// round 3
// speedup vs baseline: 1.5914x; 1.5914x over previous
#include <cuda_runtime.h>
#include <cstdint>

#define T_DIM 256
#define D_DIM 44
#define H_DIM 8
#define NPATHS 8192
#define NGROUPS 1024
#define PD 3            // prefetch distance (steps ahead)
#define RING 4          // smem ring stages

// scratch
__device__ float g_hlast[NPATHS * H_DIM];
__device__ float g_logits[NGROUPS];

__device__ __forceinline__ float fast_ex2(float x) {
    float r; asm("ex2.approx.f32 %0, %1;" : "=f"(r) : "f"(x)); return r;
}
__device__ __forceinline__ float fast_rcp(float x) {
    float r; asm("rcp.approx.f32 %0, %1;" : "=f"(r) : "f"(x)); return r;
}
// tanh(x) = 1 - 2/(1 + exp(2x))
__device__ __forceinline__ float tanh_f(float x) {
    float e = fast_ex2(2.8853900817779268f * x);
    return 1.0f - 2.0f * fast_rcp(e + 1.0f);
}

__device__ __forceinline__ unsigned int smem_u32(const void* p) {
    return (unsigned int)__cvta_generic_to_shared(p);
}
__device__ __forceinline__ void cp16_pred(unsigned int dst, const void* src, bool pred) {
    asm volatile(
        "{ .reg .pred q; setp.ne.u32 q, %2, 0;"
        " @q cp.async.ca.shared.global [%0], [%1], 16; }"
        :: "r"(dst), "l"(src), "r"((int)pred));
}
#define CP_COMMIT() asm volatile("cp.async.commit_group;" ::: "memory")
#define CP_WAIT2()  asm volatile("cp.async.wait_group 2;" ::: "memory")

// ─────────────────────────────────────────────────────────────────────────────
// LSTM recurrence: 1 warp per path, 1 warp per block (independent retirement).
// Lane g owns gate row g (0-7 i, 8-15 f, 16-23 g, 24-31 o).
// x_t staged through a 4-deep cp.async smem ring (prefetch distance 3).
// ─────────────────────────────────────────────────────────────────────────────
__global__ void __launch_bounds__(32, 24)
lstm_kernel(const float* __restrict__ x,
            const float* __restrict__ W_ih,
            const float* __restrict__ W_hh,
            const float* __restrict__ b_ih,
            const float* __restrict__ b_hh,
            const int* __restrict__ last_idx)
{
    __shared__ float4 sx[RING][11];

    const int lane = threadIdx.x;
    const int path = blockIdx.x;

    // weight rows in registers
    float wih[44];
    {
        const float4* wr = (const float4*)(W_ih + lane * 44);
        #pragma unroll
        for (int k = 0; k < 11; k++) {
            float4 v = wr[k];
            wih[4*k+0] = v.x; wih[4*k+1] = v.y; wih[4*k+2] = v.z; wih[4*k+3] = v.w;
        }
    }
    float whh[8];
    {
        const float4* wr = (const float4*)(W_hh + lane * 8);
        float4 v0 = wr[0], v1 = wr[1];
        whh[0]=v0.x; whh[1]=v0.y; whh[2]=v0.z; whh[3]=v0.w;
        whh[4]=v1.x; whh[5]=v1.y; whh[6]=v1.z; whh[7]=v1.w;
    }
    const float bias = b_ih[lane] + b_hh[lane];

    // branchless activation:  act(v) = al + be * rcp(1 + ex2(m*v))
    const bool isg = (lane >= 16) && (lane < 24);
    const float m_act  = isg ?  2.8853900817779268f : -1.4426950408889634f;
    const float al_act = isg ?  1.0f : 0.0f;
    const float be_act = isg ? -2.0f : 1.0f;

    const int    last = last_idx[path];
    const float4* xr  = (const float4*)(x + (size_t)path * T_DIM * D_DIM); // 11 float4 per step
    const int    jl   = lane & 7;

    const bool loader = (lane < 11);
    unsigned int sbase = smem_u32(&sx[0][0]);

    // prologue: prefetch x_0..x_2 (one commit group per step to keep counts aligned)
    #pragma unroll
    for (int p = 0; p < PD; p++) {
        cp16_pred(sbase + (unsigned int)(p * 11 + lane) * 16,
                  xr + (size_t)p * 11 + lane,
                  loader && (p <= last));
        CP_COMMIT();
    }

    float hvec[8];
    #pragma unroll
    for (int j = 0; j < 8; j++) hvec[j] = 0.0f;
    float c = 0.0f;

    for (int t = 0; t <= last; t++) {
        const int st = t & (RING - 1);

        CP_WAIT2();          // x_t's group (committed 3 iters back) is complete
        __syncwarp();        // make it visible to all lanes; also fences ring reuse

        // gates = bias + W_ih x_t + W_hh h  (4 accumulation chains)
        float a0 = bias, a1 = 0.f, a2 = 0.f, a3 = 0.f;
        const float4* xs = sx[st];
        #pragma unroll
        for (int k = 0; k < 11; k++) {
            float4 xv = xs[k];                      // warp-uniform broadcast LDS.128
            a0 = fmaf(wih[4*k+0], xv.x, a0);
            a1 = fmaf(wih[4*k+1], xv.y, a1);
            a2 = fmaf(wih[4*k+2], xv.z, a2);
            a3 = fmaf(wih[4*k+3], xv.w, a3);
        }
        #pragma unroll
        for (int j = 0; j < 8; j += 4) {
            a0 = fmaf(whh[j+0], hvec[j+0], a0);
            a1 = fmaf(whh[j+1], hvec[j+1], a1);
            a2 = fmaf(whh[j+2], hvec[j+2], a2);
            a3 = fmaf(whh[j+3], hvec[j+3], a3);
        }
        float acc = (a0 + a1) + (a2 + a3);

        // per-lane activation
        float u = fast_rcp(1.0f + fast_ex2(m_act * acc));
        float a = fmaf(be_act, u, al_act);

        // gather i/f/g/o for hidden index jl
        float iv = __shfl_sync(0xffffffffu, a, jl);
        float fv = __shfl_sync(0xffffffffu, a, jl + 8);
        float gv = __shfl_sync(0xffffffffu, a, jl + 16);
        float ov = __shfl_sync(0xffffffffu, a, jl + 24);

        c = fmaf(fv, c, iv * gv);
        float hl = ov * tanh_f(c);

        #pragma unroll
        for (int j = 0; j < 8; j++) hvec[j] = __shfl_sync(0xffffffffu, hl, j);

        // prefetch x_{t+PD} into the stage we just freed
        const int tp = t + PD;
        cp16_pred(sbase + (unsigned int)(((tp & (RING - 1)) * 11 + lane) * 16),
                  xr + (size_t)tp * 11 + lane,
                  loader && (tp <= last));
        CP_COMMIT();
    }

    if (lane < 8) g_hlast[path * H_DIM + lane] = hvec[lane];
}

// ─────────────────────────────────────────────────────────────────────────────
// Finalize, stage 1: per-group logit (deterministic binary-search segment sum)
// 32 blocks × 32 threads — spreads the 256 KB of g_hlast reads across SMs.
// ─────────────────────────────────────────────────────────────────────────────
__global__ void __launch_bounds__(32)
logits_kernel(const int* __restrict__ group_ids,
              const float* __restrict__ fc_W,
              const float* __restrict__ fc_b)
{
    const int g = blockIdx.x * 32 + threadIdx.x;

    float w[8];
    #pragma unroll
    for (int j = 0; j < 8; j++) w[j] = fc_W[j];

    int lo = 0, hi = NPATHS;
    while (lo < hi) { int mid = (lo + hi) >> 1; if (group_ids[mid] <  g) lo = mid + 1; else hi = mid; }
    const int start = lo;
    hi = NPATHS;
    while (lo < hi) { int mid = (lo + hi) >> 1; if (group_ids[mid] <= g) lo = mid + 1; else hi = mid; }
    const int end = lo;

    float logit = fc_b[0];
    for (int n = start; n < end; n++) {
        const float4* hp = (const float4*)(g_hlast + n * H_DIM);
        float4 h0 = hp[0], h1 = hp[1];
        float s = h0.x * w[0];
        s = fmaf(h0.y, w[1], s);
        s = fmaf(h0.z, w[2], s);
        s = fmaf(h0.w, w[3], s);
        s = fmaf(h1.x, w[4], s);
        s = fmaf(h1.y, w[5], s);
        s = fmaf(h1.z, w[6], s);
        s = fmaf(h1.w, w[7], s);
        logit += s;
    }
    g_logits[g] = logit;
}

// ─────────────────────────────────────────────────────────────────────────────
// Finalize, stage 2: softmax over the 1024 group logits (one block)
// ─────────────────────────────────────────────────────────────────────────────
__global__ void __launch_bounds__(NGROUPS)
softmax_kernel(float* __restrict__ out)
{
    __shared__ float red[NGROUPS];
    const int g = threadIdx.x;
    const float logit = g_logits[g];

    red[g] = logit;
    __syncthreads();
    #pragma unroll
    for (int off = NGROUPS / 2; off > 0; off >>= 1) {
        if (g < off) red[g] = fmaxf(red[g], red[g + off]);
        __syncthreads();
    }
    const float mx = red[0];
    __syncthreads();
    const float e = __expf(logit - mx);
    red[g] = e;
    __syncthreads();
    #pragma unroll
    for (int off = NGROUPS / 2; off > 0; off >>= 1) {
        if (g < off) red[g] += red[g + off];
        __syncthreads();
    }
    out[g] = e * fast_rcp(red[0]);
}

extern "C" void kernel_launch(void* const* d_in, const int* in_sizes, int n_in,
                              void* d_out, int out_size)
{
    const float* x      = (const float*)d_in[0];
    const float* W_ih   = (const float*)d_in[1];
    const float* W_hh   = (const float*)d_in[2];
    const float* b_ih   = (const float*)d_in[3];
    const float* b_hh   = (const float*)d_in[4];
    const float* fc_W   = (const float*)d_in[5];
    const float* fc_b   = (const float*)d_in[6];
    const int*   last_i = (const int*)d_in[7];
    const int*   gids   = (const int*)d_in[8];
    float*       out    = (float*)d_out;

    lstm_kernel<<<NPATHS, 32>>>(x, W_ih, W_hh, b_ih, b_hh, last_i);
    logits_kernel<<<NGROUPS / 32, 32>>>(gids, fc_W, fc_b);
    softmax_kernel<<<1, NGROUPS>>>(out);
}

// round 4
// speedup vs baseline: 2.1826x; 1.3715x over previous
#include <cuda_runtime.h>
#include <cstdint>

#define T_DIM 256
#define D_DIM 44
#define H_DIM 8
#define NPATHS 8192
#define NGROUPS 1024
#define PD 3            // prefetch distance (steps)
#define RING 4          // smem ring stages

// scratch
__device__ float g_hlast[NPATHS * H_DIM];
__device__ float g_logits[NGROUPS];
__device__ int   g_order[NPATHS];

__device__ __forceinline__ float fast_ex2(float x) {
    float r; asm("ex2.approx.f32 %0, %1;" : "=f"(r) : "f"(x)); return r;
}
__device__ __forceinline__ float fast_rcp(float x) {
    float r; asm("rcp.approx.f32 %0, %1;" : "=f"(r) : "f"(x)); return r;
}
// tanh(x) = 1 - 2/(1 + exp(2x))
__device__ __forceinline__ float tanh_f(float x) {
    float e = fast_ex2(2.8853900817779268f * x);
    return 1.0f - 2.0f * fast_rcp(e + 1.0f);
}

// packed f32x2 helpers (Blackwell FFMA2 path)
__device__ __forceinline__ void ffma2(unsigned long long& d, unsigned long long a, unsigned long long b) {
    asm("fma.rn.f32x2 %0, %1, %2, %0;" : "+l"(d) : "l"(a), "l"(b));
}
__device__ __forceinline__ unsigned long long add2(unsigned long long a, unsigned long long b) {
    unsigned long long r; asm("add.rn.f32x2 %0, %1, %2;" : "=l"(r) : "l"(a), "l"(b)); return r;
}
__device__ __forceinline__ float hsum2(unsigned long long v) {
    float lo, hi; asm("mov.b64 {%0,%1}, %2;" : "=f"(lo), "=f"(hi) : "l"(v)); return lo + hi;
}

__device__ __forceinline__ unsigned int smem_u32(const void* p) {
    return (unsigned int)__cvta_generic_to_shared(p);
}
__device__ __forceinline__ void cp16_pred(unsigned int dst, const void* src, bool pred) {
    asm volatile(
        "{ .reg .pred q; setp.ne.u32 q, %2, 0;"
        " @q cp.async.ca.shared.global [%0], [%1], 16; }"
        :: "r"(dst), "l"(src), "r"((int)pred));
}
#define CP_COMMIT() asm volatile("cp.async.commit_group;" ::: "memory")
#define CP_WAIT2()  asm volatile("cp.async.wait_group 2;" ::: "memory")

// ─────────────────────────────────────────────────────────────────────────────
// Counting sort of path indices by last_idx, DESCENDING (longest first).
// One block; output permutation may vary run-to-run but results are invariant
// (it only reassigns which warp processes which path).
// ─────────────────────────────────────────────────────────────────────────────
__global__ void __launch_bounds__(1024)
sort_kernel(const int* __restrict__ last_idx)
{
    __shared__ int cnt[256];
    __shared__ int off[256];
    const int tid = threadIdx.x;
    if (tid < 256) cnt[tid] = 0;
    __syncthreads();
    for (int i = tid; i < NPATHS; i += 1024) atomicAdd(&cnt[last_idx[i]], 1);
    __syncthreads();
    if (tid == 0) {
        int acc = 0;
        for (int L = 255; L >= 0; L--) { off[L] = acc; acc += cnt[L]; }
    }
    __syncthreads();
    if (tid < 256) cnt[tid] = 0;
    __syncthreads();
    for (int i = tid; i < NPATHS; i += 1024) {
        const int L = last_idx[i];
        const int pos = off[L] + atomicAdd(&cnt[L], 1);
        g_order[pos] = i;
    }
}

// ─────────────────────────────────────────────────────────────────────────────
// LSTM: 1 warp per block, TWO length-matched paths per warp.
// Lane g owns gate row g for BOTH paths (weights shared in registers).
// Input dots use packed fma.rn.f32x2; x staged via cp.async ring (PD=3).
// ─────────────────────────────────────────────────────────────────────────────
__global__ void __launch_bounds__(32, 16)
lstm_kernel(const float* __restrict__ x,
            const float* __restrict__ W_ih,
            const float* __restrict__ W_hh,
            const float* __restrict__ b_ih,
            const float* __restrict__ b_hh,
            const int* __restrict__ last_idx)
{
    __shared__ float4 sx[RING][2][11];   // ring: [stage][path-side][11 float4]
    __shared__ float  sh[16];            // h broadcast: A at [0..7], B at [8..15]

    const int lane = threadIdx.x;
    const int pA = g_order[2 * blockIdx.x];
    const int pB = g_order[2 * blockIdx.x + 1];

    // packed weight rows (shared across both paths)
    unsigned long long wihP[22];
    {
        const ulonglong2* wr = (const ulonglong2*)(W_ih + lane * 44);   // 176B rows, 16B aligned
        #pragma unroll
        for (int k = 0; k < 11; k++) {
            ulonglong2 v = wr[k];
            wihP[2*k]   = v.x;
            wihP[2*k+1] = v.y;
        }
    }
    unsigned long long whhP[4];
    {
        const ulonglong2* wr = (const ulonglong2*)(W_hh + lane * 8);
        ulonglong2 v0 = wr[0], v1 = wr[1];
        whhP[0] = v0.x; whhP[1] = v0.y; whhP[2] = v1.x; whhP[3] = v1.y;
    }
    const float bias = b_ih[lane] + b_hh[lane];
    unsigned long long biasPk;
    {
        union { unsigned long long u; float2 f; } t; t.f = make_float2(bias, 0.0f);
        biasPk = t.u;
    }

    // branchless activation:  act(v) = al + be * rcp(1 + ex2(m*v))
    const bool isg = (lane >= 16) && (lane < 24);
    const float m_act  = isg ?  2.8853900817779268f : -1.4426950408889634f;
    const float al_act = isg ?  1.0f : 0.0f;
    const float be_act = isg ? -2.0f : 1.0f;

    const int lastA = last_idx[pA];
    const int lastB = last_idx[pB];
    const int tmax  = max(lastA, lastB);

    const float4* xrA = (const float4*)(x + (size_t)pA * T_DIM * D_DIM);
    const float4* xrB = (const float4*)(x + (size_t)pB * T_DIM * D_DIM);
    const int jl = lane & 7;

    // per-lane loader mapping: lanes 0-10 load path A, lanes 16-26 load path B
    const int  side   = lane >> 4;
    const int  slot   = lane & 15;
    const bool ldr    = slot < 11;
    const float4* myx = side ? xrB : xrA;
    const int  mylast = side ? lastB : lastA;
    const unsigned int sbase = smem_u32(&sx[0][0][0]);
    const unsigned int mydst0 = (unsigned int)((side * 11 + slot) * 16);

    // prologue: prefetch steps 0..PD-1
    #pragma unroll
    for (int p = 0; p < PD; p++) {
        cp16_pred(sbase + (unsigned int)(p * 352) + mydst0,
                  myx + (size_t)p * 11 + slot,
                  ldr && (p <= mylast));
        CP_COMMIT();
    }

    unsigned long long hAp[4] = {0ull, 0ull, 0ull, 0ull};
    unsigned long long hBp[4] = {0ull, 0ull, 0ull, 0ull};
    float cA = 0.f, cB = 0.f, hlA = 0.f, hlB = 0.f;

    for (int t = 0; t <= tmax; t++) {
        const int stage = t & (RING - 1);

        CP_WAIT2();
        __syncwarp();

        const ulonglong2* xsA = (const ulonglong2*)&sx[stage][0][0];
        const ulonglong2* xsB = (const ulonglong2*)&sx[stage][1][0];

        // two independent packed gate dots (ILP=2 across paths)
        unsigned long long a0A = biasPk, a1A = 0ull;
        unsigned long long a0B = biasPk, a1B = 0ull;
        #pragma unroll
        for (int k = 0; k < 11; k++) {
            ulonglong2 xvA = xsA[k];
            ulonglong2 xvB = xsB[k];
            ffma2(a0A, wihP[2*k],   xvA.x);
            ffma2(a1A, wihP[2*k+1], xvA.y);
            ffma2(a0B, wihP[2*k],   xvB.x);
            ffma2(a1B, wihP[2*k+1], xvB.y);
        }
        ffma2(a0A, whhP[0], hAp[0]); ffma2(a1A, whhP[1], hAp[1]);
        ffma2(a0A, whhP[2], hAp[2]); ffma2(a1A, whhP[3], hAp[3]);
        ffma2(a0B, whhP[0], hBp[0]); ffma2(a1B, whhP[1], hBp[1]);
        ffma2(a0B, whhP[2], hBp[2]); ffma2(a1B, whhP[3], hBp[3]);
        const float accA = hsum2(add2(a0A, a1A));
        const float accB = hsum2(add2(a0B, a1B));

        // activations
        const float uA = fast_rcp(1.0f + fast_ex2(m_act * accA));
        const float aA = fmaf(be_act, uA, al_act);
        const float uB = fast_rcp(1.0f + fast_ex2(m_act * accB));
        const float aB = fmaf(be_act, uB, al_act);

        // gather gates
        const float ivA = __shfl_sync(0xffffffffu, aA, jl);
        const float fvA = __shfl_sync(0xffffffffu, aA, jl + 8);
        const float gvA = __shfl_sync(0xffffffffu, aA, jl + 16);
        const float ovA = __shfl_sync(0xffffffffu, aA, jl + 24);
        const float ivB = __shfl_sync(0xffffffffu, aB, jl);
        const float fvB = __shfl_sync(0xffffffffu, aB, jl + 8);
        const float gvB = __shfl_sync(0xffffffffu, aB, jl + 16);
        const float ovB = __shfl_sync(0xffffffffu, aB, jl + 24);

        // cell/hidden updates, predicated per path (frozen when past its end)
        const bool okA = (t <= lastA);
        const bool okB = (t <= lastB);
        const float cAn  = fmaf(fvA, cA, ivA * gvA);
        const float cBn  = fmaf(fvB, cB, ivB * gvB);
        const float hlAn = ovA * tanh_f(cAn);
        const float hlBn = ovB * tanh_f(cBn);
        cA  = okA ? cAn  : cA;
        hlA = okA ? hlAn : hlA;
        cB  = okB ? cBn  : cB;
        hlB = okB ? hlBn : hlB;

        // prefetch t+PD (one warp-wide predicated LDGSTS covers both paths)
        const int tp = t + PD;
        cp16_pred(sbase + (unsigned int)((tp & (RING - 1)) * 352) + mydst0,
                  myx + (size_t)tp * 11 + slot,
                  ldr && (tp <= mylast));
        CP_COMMIT();

        // broadcast h via shared memory (lanes 0-7: A, lanes 8-15: B)
        if (lane < 16) sh[lane] = (lane < 8) ? hlA : hlB;
        __syncwarp();
        {
            const ulonglong2* shp = (const ulonglong2*)sh;
            ulonglong2 a01 = shp[0], a23 = shp[1];
            ulonglong2 b01 = shp[2], b23 = shp[3];
            hAp[0] = a01.x; hAp[1] = a01.y; hAp[2] = a23.x; hAp[3] = a23.y;
            hBp[0] = b01.x; hBp[1] = b01.y; hBp[2] = b23.x; hBp[3] = b23.y;
        }
    }

    if (lane < 8)                     g_hlast[pA * H_DIM + lane]       = hlA;
    else if (lane < 16)               g_hlast[pB * H_DIM + (lane - 8)] = hlB;
}

// ─────────────────────────────────────────────────────────────────────────────
// Finalize stage 1: per-group logit (binary-search segment sum, deterministic)
// ─────────────────────────────────────────────────────────────────────────────
__global__ void __launch_bounds__(32)
logits_kernel(const int* __restrict__ group_ids,
              const float* __restrict__ fc_W,
              const float* __restrict__ fc_b)
{
    const int g = blockIdx.x * 32 + threadIdx.x;

    float w[8];
    #pragma unroll
    for (int j = 0; j < 8; j++) w[j] = fc_W[j];

    int lo = 0, hi = NPATHS;
    while (lo < hi) { int mid = (lo + hi) >> 1; if (group_ids[mid] <  g) lo = mid + 1; else hi = mid; }
    const int start = lo;
    hi = NPATHS;
    while (lo < hi) { int mid = (lo + hi) >> 1; if (group_ids[mid] <= g) lo = mid + 1; else hi = mid; }
    const int end = lo;

    float logit = fc_b[0];
    for (int n = start; n < end; n++) {
        const float4* hp = (const float4*)(g_hlast + n * H_DIM);
        float4 h0 = hp[0], h1 = hp[1];
        float s = h0.x * w[0];
        s = fmaf(h0.y, w[1], s);
        s = fmaf(h0.z, w[2], s);
        s = fmaf(h0.w, w[3], s);
        s = fmaf(h1.x, w[4], s);
        s = fmaf(h1.y, w[5], s);
        s = fmaf(h1.z, w[6], s);
        s = fmaf(h1.w, w[7], s);
        logit += s;
    }
    g_logits[g] = logit;
}

// ─────────────────────────────────────────────────────────────────────────────
// Finalize stage 2: softmax over the 1024 group logits
// ─────────────────────────────────────────────────────────────────────────────
__global__ void __launch_bounds__(NGROUPS)
softmax_kernel(float* __restrict__ out)
{
    __shared__ float red[NGROUPS];
    const int g = threadIdx.x;
    const float logit = g_logits[g];

    red[g] = logit;
    __syncthreads();
    #pragma unroll
    for (int off = NGROUPS / 2; off > 0; off >>= 1) {
        if (g < off) red[g] = fmaxf(red[g], red[g + off]);
        __syncthreads();
    }
    const float mx = red[0];
    __syncthreads();
    const float e = __expf(logit - mx);
    red[g] = e;
    __syncthreads();
    #pragma unroll
    for (int off = NGROUPS / 2; off > 0; off >>= 1) {
        if (g < off) red[g] += red[g + off];
        __syncthreads();
    }
    out[g] = e * fast_rcp(red[0]);
}

extern "C" void kernel_launch(void* const* d_in, const int* in_sizes, int n_in,
                              void* d_out, int out_size)
{
    const float* x      = (const float*)d_in[0];
    const float* W_ih   = (const float*)d_in[1];
    const float* W_hh   = (const float*)d_in[2];
    const float* b_ih   = (const float*)d_in[3];
    const float* b_hh   = (const float*)d_in[4];
    const float* fc_W   = (const float*)d_in[5];
    const float* fc_b   = (const float*)d_in[6];
    const int*   last_i = (const int*)d_in[7];
    const int*   gids   = (const int*)d_in[8];
    float*       out    = (float*)d_out;

    sort_kernel<<<1, 1024>>>(last_i);
    lstm_kernel<<<NPATHS / 2, 32>>>(x, W_ih, W_hh, b_ih, b_hh, last_i);
    logits_kernel<<<NGROUPS / 32, 32>>>(gids, fc_W, fc_b);
    softmax_kernel<<<1, NGROUPS>>>(out);
}

// round 5
// speedup vs baseline: 2.3141x; 1.0603x over previous
#include <cuda_runtime.h>
#include <cstdint>

#define T_DIM 256
#define D_DIM 44
#define H_DIM 8
#define NPATHS 8192
#define NGROUPS 1024
#define RING 4

// scratch
__device__ float g_hlast[NPATHS * H_DIM];
__device__ int   g_order[NPATHS];

__device__ __forceinline__ float fast_ex2(float x) {
    float r; asm("ex2.approx.f32 %0, %1;" : "=f"(r) : "f"(x)); return r;
}
__device__ __forceinline__ float fast_rcp(float x) {
    float r; asm("rcp.approx.f32 %0, %1;" : "=f"(r) : "f"(x)); return r;
}
// tanh(x) = 1 - 2/(1 + exp(2x))
__device__ __forceinline__ float tanh_f(float x) {
    float e = fast_ex2(2.8853900817779268f * x);
    return 1.0f - 2.0f * fast_rcp(e + 1.0f);
}

// packed f32x2 helpers
__device__ __forceinline__ void ffma2(unsigned long long& d, unsigned long long a, unsigned long long b) {
    asm("fma.rn.f32x2 %0, %1, %2, %0;" : "+l"(d) : "l"(a), "l"(b));
}
__device__ __forceinline__ unsigned long long add2(unsigned long long a, unsigned long long b) {
    unsigned long long r; asm("add.rn.f32x2 %0, %1, %2;" : "=l"(r) : "l"(a), "l"(b)); return r;
}
__device__ __forceinline__ float hsum2(unsigned long long v) {
    float lo, hi; asm("mov.b64 {%0,%1}, %2;" : "=f"(lo), "=f"(hi) : "l"(v)); return lo + hi;
}

__device__ __forceinline__ unsigned int smem_u32(const void* p) {
    return (unsigned int)__cvta_generic_to_shared(p);
}
__device__ __forceinline__ void cp16_pred(unsigned int dst, const void* src, bool pred) {
    asm volatile(
        "{ .reg .pred q; setp.ne.u32 q, %2, 0;"
        " @q cp.async.ca.shared.global [%0], [%1], 16; }"
        :: "r"(dst), "l"(src), "r"((int)pred));
}
#define CP_COMMIT() asm volatile("cp.async.commit_group;" ::: "memory")
#define CP_WAIT2()  asm volatile("cp.async.wait_group 2;" ::: "memory")

// ─────────────────────────────────────────────────────────────────────────────
// Counting sort of path indices by last_idx DESCENDING (longest first).
// ─────────────────────────────────────────────────────────────────────────────
__global__ void __launch_bounds__(1024)
sort_kernel(const int* __restrict__ last_idx)
{
    __shared__ int cnt[256];
    __shared__ int off[256];
    const int tid = threadIdx.x;
    if (tid < 256) cnt[tid] = 0;
    __syncthreads();
    for (int i = tid; i < NPATHS; i += 1024) atomicAdd(&cnt[last_idx[i]], 1);
    __syncthreads();
    if (tid == 0) {
        int acc = 0;
        for (int L = 255; L >= 0; L--) { off[L] = acc; acc += cnt[L]; }
    }
    __syncthreads();
    if (tid < 256) cnt[tid] = 0;
    __syncthreads();
    for (int i = tid; i < NPATHS; i += 1024) {
        const int L = last_idx[i];
        const int pos = off[L] + atomicAdd(&cnt[L], 1);
        g_order[pos] = i;
    }
}

// ─────────────────────────────────────────────────────────────────────────────
// LSTM: 1 warp/block, two length-matched paths per warp, software-pipelined:
// the W_ih·x_{t+1} dot (68 independent instrs) issues in the stall shadows of
// step t's recurrence chain. One __syncwarp per iteration; h broadcast via
// parity-double-buffered smem.
// ─────────────────────────────────────────────────────────────────────────────
__global__ void __launch_bounds__(32, 16)
lstm_kernel(const float* __restrict__ x,
            const float* __restrict__ W_ih,
            const float* __restrict__ W_hh,
            const float* __restrict__ b_ih,
            const float* __restrict__ b_hh,
            const int* __restrict__ last_idx)
{
    __shared__ float4 sx[RING][2][11];   // x ring: [stage][side][11 float4]
    __shared__ float  sh[2][16];         // h broadcast, parity double-buffered

    const int lane = threadIdx.x;
    const int pA = g_order[2 * blockIdx.x];
    const int pB = g_order[2 * blockIdx.x + 1];

    // packed weights (shared by both paths)
    unsigned long long wihP[22];
    {
        const ulonglong2* wr = (const ulonglong2*)(W_ih + lane * 44);
        #pragma unroll
        for (int k = 0; k < 11; k++) {
            ulonglong2 v = wr[k];
            wihP[2*k]   = v.x;
            wihP[2*k+1] = v.y;
        }
    }
    unsigned long long whhP[4];
    {
        const ulonglong2* wr = (const ulonglong2*)(W_hh + lane * 8);
        ulonglong2 v0 = wr[0], v1 = wr[1];
        whhP[0] = v0.x; whhP[1] = v0.y; whhP[2] = v1.x; whhP[3] = v1.y;
    }
    const float bias = b_ih[lane] + b_hh[lane];
    unsigned long long biasPk;
    {
        union { unsigned long long u; float2 f; } t; t.f = make_float2(bias, 0.0f);
        biasPk = t.u;
    }

    // branchless activation:  act(v) = al + be * rcp(1 + ex2(m*v))
    const bool isg = (lane >= 16) && (lane < 24);
    const float m_act  = isg ?  2.8853900817779268f : -1.4426950408889634f;
    const float al_act = isg ?  1.0f : 0.0f;
    const float be_act = isg ? -2.0f : 1.0f;

    const int lastA = last_idx[pA];
    const int lastB = last_idx[pB];
    const int tmax  = max(lastA, lastB);

    const float4* xrA = (const float4*)(x + (size_t)pA * T_DIM * D_DIM);
    const float4* xrB = (const float4*)(x + (size_t)pB * T_DIM * D_DIM);
    const int jl = lane & 7;

    // loader mapping: lanes 0-10 -> path A slots, lanes 16-26 -> path B slots
    const int  side   = lane >> 4;
    const int  slot   = lane & 15;
    const bool ldr    = slot < 11;
    const float4* myx = side ? xrB : xrA;
    const int  mylast = side ? lastB : lastA;
    const unsigned int sbase  = smem_u32(&sx[0][0][0]);
    const unsigned int mydst0 = (unsigned int)((side * 11 + slot) * 16);

    // prologue: prefetch s = 0..3 (one commit group per step)
    #pragma unroll
    for (int p = 0; p < RING; p++) {
        cp16_pred(sbase + (unsigned int)(p * 352) + mydst0,
                  myx + (size_t)p * 11 + slot,
                  ldr && (p <= mylast));
        CP_COMMIT();
    }

    unsigned long long hAp[4] = {0ull,0ull,0ull,0ull};
    unsigned long long hBp[4] = {0ull,0ull,0ull,0ull};
    float cA = 0.f, cB = 0.f, hlA = 0.f, hlB = 0.f;

    // initial xd(0): wait for s=0,1; compute dot for step 0
    unsigned long long xd0A, xd1A, xd0B, xd1B;
    CP_WAIT2();
    __syncwarp();
    {
        const ulonglong2* xsA = (const ulonglong2*)&sx[0][0][0];
        const ulonglong2* xsB = (const ulonglong2*)&sx[0][1][0];
        xd0A = biasPk; xd1A = 0ull; xd0B = biasPk; xd1B = 0ull;
        #pragma unroll
        for (int k = 0; k < 11; k++) {
            ulonglong2 xvA = xsA[k];
            ulonglong2 xvB = xsB[k];
            ffma2(xd0A, wihP[2*k],   xvA.x);
            ffma2(xd1A, wihP[2*k+1], xvA.y);
            ffma2(xd0B, wihP[2*k],   xvB.x);
            ffma2(xd1B, wihP[2*k+1], xvB.y);
        }
    }

    for (int t = 0; t <= tmax; t++) {
        // ── recurrence chain for step t (short) ──
        ffma2(xd0A, whhP[0], hAp[0]); ffma2(xd1A, whhP[1], hAp[1]);
        ffma2(xd0A, whhP[2], hAp[2]); ffma2(xd1A, whhP[3], hAp[3]);
        ffma2(xd0B, whhP[0], hBp[0]); ffma2(xd1B, whhP[1], hBp[1]);
        ffma2(xd0B, whhP[2], hBp[2]); ffma2(xd1B, whhP[3], hBp[3]);
        const float accA = hsum2(add2(xd0A, xd1A));
        const float accB = hsum2(add2(xd0B, xd1B));

        const float uA = fast_rcp(1.0f + fast_ex2(m_act * accA));
        const float aA = fmaf(be_act, uA, al_act);
        const float uB = fast_rcp(1.0f + fast_ex2(m_act * accB));
        const float aB = fmaf(be_act, uB, al_act);

        const float ivA = __shfl_sync(0xffffffffu, aA, jl);
        const float fvA = __shfl_sync(0xffffffffu, aA, jl + 8);
        const float gvA = __shfl_sync(0xffffffffu, aA, jl + 16);
        const float ovA = __shfl_sync(0xffffffffu, aA, jl + 24);
        const float ivB = __shfl_sync(0xffffffffu, aB, jl);
        const float fvB = __shfl_sync(0xffffffffu, aB, jl + 8);
        const float gvB = __shfl_sync(0xffffffffu, aB, jl + 16);
        const float ovB = __shfl_sync(0xffffffffu, aB, jl + 24);

        const bool okA = (t <= lastA);
        const bool okB = (t <= lastB);
        const float cAn  = fmaf(fvA, cA, ivA * gvA);
        const float cBn  = fmaf(fvB, cB, ivB * gvB);
        const float hlAn = ovA * tanh_f(cAn);
        const float hlBn = ovB * tanh_f(cBn);
        cA  = okA ? cAn  : cA;
        hlA = okA ? hlAn : hlA;
        cB  = okB ? cBn  : cB;
        hlB = okB ? hlBn : hlB;

        // publish h (parity buffer)
        if (lane < 16) sh[t & 1][lane] = (lane < 8) ? hlA : hlB;

        // x_{t+1} complete + h visible
        CP_WAIT2();
        __syncwarp();

        // ── independent work: xd(t+1) — fills the chain's stall shadows ──
        {
            const int stg = (t + 1) & (RING - 1);
            const ulonglong2* xsA = (const ulonglong2*)&sx[stg][0][0];
            const ulonglong2* xsB = (const ulonglong2*)&sx[stg][1][0];
            xd0A = biasPk; xd1A = 0ull; xd0B = biasPk; xd1B = 0ull;
            #pragma unroll
            for (int k = 0; k < 11; k++) {
                ulonglong2 xvA = xsA[k];
                ulonglong2 xvB = xsB[k];
                ffma2(xd0A, wihP[2*k],   xvA.x);
                ffma2(xd1A, wihP[2*k+1], xvA.y);
                ffma2(xd0B, wihP[2*k],   xvB.x);
                ffma2(xd1B, wihP[2*k+1], xvB.y);
            }
        }

        // reload packed h
        {
            const ulonglong2* shp = (const ulonglong2*)&sh[t & 1][0];
            ulonglong2 a01 = shp[0], a23 = shp[1];
            hAp[0] = a01.x; hAp[1] = a01.y; hAp[2] = a23.x; hAp[3] = a23.y;
            ulonglong2 b01 = shp[2], b23 = shp[3];
            hBp[0] = b01.x; hBp[1] = b01.y; hBp[2] = b23.x; hBp[3] = b23.y;
        }

        // prefetch s = t+4 into the stage consumed at iter t-1 (long since read)
        const int tp = t + RING;
        cp16_pred(sbase + (unsigned int)(((tp & (RING - 1)) * 352)) + mydst0,
                  myx + (size_t)tp * 11 + slot,
                  ldr && (tp <= mylast));
        CP_COMMIT();
    }

    if (lane < 8)        g_hlast[pA * H_DIM + lane]       = hlA;
    else if (lane < 16)  g_hlast[pB * H_DIM + (lane - 8)] = hlB;
}

// ─────────────────────────────────────────────────────────────────────────────
// Fused finalize: per-group logit (binary-search segment sum) + block softmax.
// One 1024-thread block; shfl-based reductions (deterministic).
// ─────────────────────────────────────────────────────────────────────────────
__global__ void __launch_bounds__(NGROUPS)
finalize_kernel(const int* __restrict__ group_ids,
                const float* __restrict__ fc_W,
                const float* __restrict__ fc_b,
                float* __restrict__ out)
{
    __shared__ float warpred[32];
    __shared__ float bc;

    const int g   = threadIdx.x;
    const int wid = g >> 5;
    const int lid = g & 31;

    float w[8];
    #pragma unroll
    for (int j = 0; j < 8; j++) w[j] = fc_W[j];

    int lo = 0, hi = NPATHS;
    while (lo < hi) { int mid = (lo + hi) >> 1; if (group_ids[mid] <  g) lo = mid + 1; else hi = mid; }
    const int start = lo;
    hi = NPATHS;
    while (lo < hi) { int mid = (lo + hi) >> 1; if (group_ids[mid] <= g) lo = mid + 1; else hi = mid; }
    const int end = lo;

    float logit = fc_b[0];
    for (int n = start; n < end; n++) {
        const float4* hp = (const float4*)(g_hlast + n * H_DIM);
        float4 h0 = hp[0], h1 = hp[1];
        float s = h0.x * w[0];
        s = fmaf(h0.y, w[1], s);
        s = fmaf(h0.z, w[2], s);
        s = fmaf(h0.w, w[3], s);
        s = fmaf(h1.x, w[4], s);
        s = fmaf(h1.y, w[5], s);
        s = fmaf(h1.z, w[6], s);
        s = fmaf(h1.w, w[7], s);
        logit += s;
    }

    // block max
    float m = logit;
    #pragma unroll
    for (int off = 16; off > 0; off >>= 1) m = fmaxf(m, __shfl_xor_sync(0xffffffffu, m, off));
    if (lid == 0) warpred[wid] = m;
    __syncthreads();
    if (wid == 0) {
        float v = warpred[lid];
        #pragma unroll
        for (int off = 16; off > 0; off >>= 1) v = fmaxf(v, __shfl_xor_sync(0xffffffffu, v, off));
        if (lid == 0) bc = v;
    }
    __syncthreads();
    const float mx = bc;

    const float e = __expf(logit - mx);

    // block sum
    float s = e;
    #pragma unroll
    for (int off = 16; off > 0; off >>= 1) s += __shfl_xor_sync(0xffffffffu, s, off);
    __syncthreads();               // warp0 done reading warpred (max phase)
    if (lid == 0) warpred[wid] = s;
    __syncthreads();
    if (wid == 0) {
        float v = warpred[lid];
        #pragma unroll
        for (int off = 16; off > 0; off >>= 1) v += __shfl_xor_sync(0xffffffffu, v, off);
        if (lid == 0) bc = v;
    }
    __syncthreads();

    out[g] = e * fast_rcp(bc);
}

extern "C" void kernel_launch(void* const* d_in, const int* in_sizes, int n_in,
                              void* d_out, int out_size)
{
    const float* x      = (const float*)d_in[0];
    const float* W_ih   = (const float*)d_in[1];
    const float* W_hh   = (const float*)d_in[2];
    const float* b_ih   = (const float*)d_in[3];
    const float* b_hh   = (const float*)d_in[4];
    const float* fc_W   = (const float*)d_in[5];
    const float* fc_b   = (const float*)d_in[6];
    const int*   last_i = (const int*)d_in[7];
    const int*   gids   = (const int*)d_in[8];
    float*       out    = (float*)d_out;

    sort_kernel<<<1, 1024>>>(last_i);
    lstm_kernel<<<NPATHS / 2, 32>>>(x, W_ih, W_hh, b_ih, b_hh, last_i);
    finalize_kernel<<<1, NGROUPS>>>(gids, fc_W, fc_b, out);
}